// round 5
// baseline (speedup 1.0000x reference)
#include <cuda_runtime.h>
#include <cstdint>

#define FH   45
#define FW   80
#define CC   64
#define BB   16
#define NN   2784
#define JOUT 75
#define JP   80          // P padded j-dim (20 float4)
#define ODIM 77
#define G    320         // anchors per k3 block
#define T3   608         // 19 warps = 32 agrp * 19 lanes
#define SJP  76          // smem slab j-stride (19 float4)

__device__ float  g_WW[FH * CC * JP];
__device__ float  g_Bh[FH * JP];
__device__ float4 g_P[BB * FH * FW * (JP/4)];
__device__ int    g_wT[FH * NN];     // [h][n]: column index or -1 if invalid

// ---------- f32x2 helpers (sm_103a packed fp32) ----------
__device__ __forceinline__ unsigned long long pack2(float a, float b) {
    unsigned long long r;
    asm("mov.b64 %0, {%1, %2};" : "=l"(r) : "f"(a), "f"(b));
    return r;
}
__device__ __forceinline__ void unpack2(unsigned long long v, float& a, float& b) {
    asm("mov.b64 {%0, %1}, %2;" : "=f"(a), "=f"(b) : "l"(v));
}
__device__ __forceinline__ unsigned long long fma2(unsigned long long a,
                                                   unsigned long long b,
                                                   unsigned long long c) {
    unsigned long long r;
    asm("fma.rn.f32x2 %0, %1, %2, %3;" : "=l"(r) : "l"(a), "l"(b), "l"(c));
    return r;
}
// ---------- cp.async helpers ----------
__device__ __forceinline__ void cp16(void* smem_dst, const void* gsrc) {
    uint32_t d = (uint32_t)__cvta_generic_to_shared(smem_dst);
    asm volatile("cp.async.cg.shared.global [%0], [%1], 16;" :: "r"(d), "l"(gsrc) : "memory");
}
__device__ __forceinline__ void cp_commit() {
    asm volatile("cp.async.commit_group;" ::: "memory");
}
__device__ __forceinline__ void cp_wait0() {
    asm volatile("cp.async.wait_group 0;" ::: "memory");
}

// ---------------------------------------------------------------------------
// k0: transpose cut_xs/invalid into g_wT[h][n] (sentinel -1 for invalid)
// ---------------------------------------------------------------------------
__global__ void k_xpose(const int* __restrict__ cut_xs,
                        const unsigned char* __restrict__ invalid) {
    int idx = blockIdx.x * 256 + threadIdx.x;
    if (idx >= FH * NN) return;
    int h = idx / NN, n = idx - h * NN;
    int xv = cut_xs[n * FH + h];
    xv = min(max(xv, 0), FW - 1);
    g_wT[idx] = invalid[n * FH + h] ? -1 : xv;
}

// ---------------------------------------------------------------------------
// k1: fold conv into head weights. grid (FH, 4): 16-ci slice per block.
// ---------------------------------------------------------------------------
__global__ void k_prep(const float* __restrict__ conv_w, const float* __restrict__ conv_b,
                       const float* __restrict__ cls_w,  const float* __restrict__ reg_w) {
    int h  = blockIdx.x;
    int by = blockIdx.y;            // ci slice
    int j  = threadIdx.x;           // 0..79
    int ty = threadIdx.y;           // 0..3
    __shared__ float sW[CC][JP];    // Wcat[o][j] for this h
    __shared__ float sc[CC][16];    // conv_w[o][by*16 + cl]

    int tid = ty * JP + j;          // 0..319
    for (int i = tid; i < CC * 16; i += 320) {
        int o = i >> 4, cl = i & 15;
        sc[o][cl] = conv_w[o * CC + by * 16 + cl];
    }
    for (int o = ty; o < CC; o += 4) {
        float v = 0.f;
        if (j < 2)          v = cls_w[(o * FH + h) * 2 + j];
        else if (j < JOUT)  v = reg_w[(o * FH + h) * 73 + (j - 2)];
        sW[o][j] = v;
    }
    __syncthreads();

    float a0 = 0.f, a1 = 0.f, a2 = 0.f, a3 = 0.f, accb = 0.f;
    bool do_b = (by == 0 && ty == 0);
#pragma unroll 8
    for (int o = 0; o < CC; o++) {
        float wv = sW[o][j];
        float4 c = *(const float4*)&sc[o][ty * 4];
        a0 += c.x * wv; a1 += c.y * wv; a2 += c.z * wv; a3 += c.w * wv;
        if (do_b) accb += conv_b[o] * wv;
    }
    int ci = by * 16 + ty * 4;
    g_WW[(h * CC + ci + 0) * JP + j] = a0;
    g_WW[(h * CC + ci + 1) * JP + j] = a1;
    g_WW[(h * CC + ci + 2) * JP + j] = a2;
    g_WW[(h * CC + ci + 3) * JP + j] = a3;
    if (do_b) g_Bh[h * JP + j] = accb;
}

// ---------------------------------------------------------------------------
// k2: P[b,h,w,j] = sum_ci x[b,ci,h,w]*WW[ci,h,j] + Bh[h,j]   (f32x2 packed)
// block (20,16): 4j x 5w tile per thread. grid (FH, BB).
// ---------------------------------------------------------------------------
__global__ void k_pcompute(const float* __restrict__ x) {
    int h = blockIdx.x, b = blockIdx.y;
    __shared__ float sx[CC][FW];
    __shared__ float sw[CC][JP];
    int tid = threadIdx.y * 20 + threadIdx.x;   // 0..319

    const float* xb  = x + ((b * CC) * FH + h) * FW;
    const float* wwh = g_WW + h * CC * JP;
    for (int i = tid; i < CC * FW; i += 320) {
        int ci = i / FW, w = i - ci * FW;
        sx[ci][w] = xb[ci * FH * FW + w];
        sw[ci][w] = wwh[i];
    }
    __syncthreads();

    int j0 = threadIdx.x * 4;   // 20*4 = 80 j
    int w0 = threadIdx.y * 5;   // 16*5 = 80 w
    unsigned long long acc0[5], acc1[5];
    unsigned long long z = pack2(0.f, 0.f);
#pragma unroll
    for (int v = 0; v < 5; v++) { acc0[v] = z; acc1[v] = z; }

#pragma unroll 4
    for (int ci = 0; ci < CC; ci++) {
        unsigned long long wa = *(const unsigned long long*)&sw[ci][j0];
        unsigned long long wb = *(const unsigned long long*)&sw[ci][j0 + 2];
#pragma unroll
        for (int v = 0; v < 5; v++) {
            float xs = sx[ci][w0 + v];
            unsigned long long xv = pack2(xs, xs);
            acc0[v] = fma2(xv, wa, acc0[v]);
            acc1[v] = fma2(xv, wb, acc1[v]);
        }
    }

    float4 bh = *(const float4*)&g_Bh[h * JP + j0];
    float* Pp = (float*)g_P + (size_t)((b * FH + h) * FW) * JP;
#pragma unroll
    for (int v = 0; v < 5; v++) {
        float4 r;
        float p0, p1;
        unpack2(acc0[v], p0, p1); r.x = p0 + bh.x; r.y = p1 + bh.y;
        unpack2(acc1[v], p0, p1); r.z = p0 + bh.z; r.w = p1 + bh.w;
        *(float4*)&Pp[(w0 + v) * JP + j0] = r;
    }
}

// ---------------------------------------------------------------------------
// k3: slab gather. grid (9, BB); block 608 = 32 anchor-groups x 19 j4-lanes.
// Per h: stage P[b,h,*,*] slab in smem (cp.async dbl-buffer), anchors read
// their column from smem. acc[k] per thread: anchor a = agrp + 32k.
// ---------------------------------------------------------------------------
__global__ void __launch_bounds__(T3, 1)
k_gather(const float* __restrict__ cls_b, const float* __restrict__ reg_b,
         const float* __restrict__ anchors, float* __restrict__ out) {
    __shared__ float sP[2][FW][SJP];   // 2 x 80 x 76 floats = 48640 B

    int b   = blockIdx.y;
    int n0  = blockIdx.x * G;
    int tid = threadIdx.x;
    int lane = tid % 19;           // j4 lane
    int agrp = tid / 19;           // 0..31

    const float4* Pslab0 = g_P + (size_t)(b * FH) * FW * (JP / 4);

    // per-thread activity mask + bias init
    bool act[10];
    float4 acc[10];
    float bias[4];
#pragma unroll
    for (int u = 0; u < 4; u++) {
        int j = 4 * lane + u;
        bias[u] = (j < 2) ? cls_b[j] : ((j < JOUT) ? reg_b[j - 2] : 0.f);
    }
#pragma unroll
    for (int k = 0; k < 10; k++) {
        act[k] = (n0 + agrp + 32 * k) < NN;
        acc[k] = make_float4(bias[0], bias[1], bias[2], bias[3]);
    }
    const int* gw = g_wT + n0 + agrp;

    // prefetch slab h=0 into buf 0
    {
        const float4* src = Pslab0;   // h = 0
        for (int i = tid; i < FW * 19; i += T3) {
            int w = i / 19, jj = i - w * 19;
            cp16(&sP[0][w][jj * 4], src + w * (JP / 4) + jj);
        }
        cp_commit();
    }
    cp_wait0();
    __syncthreads();

    int buf = 0;
    for (int h = 0; h < FH; h++) {
        if (h + 1 < FH) {
            const float4* src = Pslab0 + (size_t)(h + 1) * FW * (JP / 4);
            int nb = buf ^ 1;
            for (int i = tid; i < FW * 19; i += T3) {
                int w = i / 19, jj = i - w * 19;
                cp16(&sP[nb][w][jj * 4], src + w * (JP / 4) + jj);
            }
        }
        cp_commit();

        int wv[10];
#pragma unroll
        for (int k = 0; k < 10; k++)
            wv[k] = act[k] ? gw[h * NN + 32 * k] : -1;

#pragma unroll
        for (int k = 0; k < 10; k++) {
            if (wv[k] >= 0) {
                float4 p = *(const float4*)&sP[buf][wv[k]][lane * 4];
                acc[k].x += p.x; acc[k].y += p.y; acc[k].z += p.z; acc[k].w += p.w;
            }
        }

        cp_wait0();
        __syncthreads();
        buf ^= 1;
    }

    // epilogue
#pragma unroll
    for (int k = 0; k < 10; k++) {
        if (!act[k]) continue;
        int n = n0 + agrp + 32 * k;
        int obase = (b * NN + n) * ODIM;
        const float* an = anchors + n * ODIM;
        float av[4] = {acc[k].x, acc[k].y, acc[k].z, acc[k].w};
#pragma unroll
        for (int u = 0; u < 4; u++) {
            int j = 4 * lane + u;
            if (j < 2)          out[obase + j]     = av[u];
            else if (j < JOUT)  out[obase + j + 2] = an[j + 2] + av[u];
        }
        if (lane == 0) {
            out[obase + 2] = an[2];
            out[obase + 3] = an[3];
        }
    }
}

// ---------------------------------------------------------------------------
extern "C" void kernel_launch(void* const* d_in, const int* in_sizes, int n_in,
                              void* d_out, int out_size) {
    const float* x       = (const float*)d_in[0];
    const float* conv_w  = (const float*)d_in[1];
    const float* conv_b  = (const float*)d_in[2];
    const float* cls_w   = (const float*)d_in[3];
    const float* cls_b   = (const float*)d_in[4];
    const float* reg_w   = (const float*)d_in[5];
    const float* reg_b   = (const float*)d_in[6];
    const float* anchors = (const float*)d_in[7];
    const int*   cut_xs  = (const int*)d_in[8];
    const unsigned char* invalid = (const unsigned char*)d_in[9];
    float* out = (float*)d_out;

    k_xpose   <<<(FH * NN + 255) / 256, 256>>>(cut_xs, invalid);
    k_prep    <<<dim3(FH, 4),  dim3(80, 4)>>>(conv_w, conv_b, cls_w, reg_w);
    k_pcompute<<<dim3(FH, BB), dim3(20, 16)>>>(x);
    k_gather  <<<dim3((NN + G - 1) / G, BB), T3>>>(cls_b, reg_b, anchors, out);
}

// round 10
// speedup vs baseline: 1.4418x; 1.4418x over previous
#include <cuda_runtime.h>
#include <cstdint>

#define FH   45
#define FW   80
#define CC   64
#define BB   16
#define NN   2784
#define JOUT 75
#define JP   80          // P padded j-dim (20 float4)
#define ODIM 77

__device__ float  g_WW[FH * CC * JP];
__device__ float  g_Bh[FH * JP];
__device__ float4 g_P[BB * FH * FW * (JP/4)];
__device__ int    g_off[NN * FH];    // compacted valid offsets per anchor
__device__ int    g_cnt[NN];         // valid count per anchor

// ---------- f32x2 helpers (sm_103a packed fp32) ----------
__device__ __forceinline__ unsigned long long pack2(float a, float b) {
    unsigned long long r;
    asm("mov.b64 %0, {%1, %2};" : "=l"(r) : "f"(a), "f"(b));
    return r;
}
__device__ __forceinline__ void unpack2(unsigned long long v, float& a, float& b) {
    asm("mov.b64 {%0, %1}, %2;" : "=f"(a), "=f"(b) : "l"(v));
}
__device__ __forceinline__ unsigned long long fma2(unsigned long long a,
                                                   unsigned long long b,
                                                   unsigned long long c) {
    unsigned long long r;
    asm("fma.rn.f32x2 %0, %1, %2, %3;" : "=l"(r) : "l"(a), "l"(b), "l"(c));
    return r;
}

// ---------------------------------------------------------------------------
// k0: per-anchor compaction. Thread per anchor: build list of
// (h*FW + x)*(JP/4) for valid h, store count.
// ---------------------------------------------------------------------------
__global__ void k_xpose(const int* __restrict__ cut_xs,
                        const unsigned char* __restrict__ invalid) {
    int n = blockIdx.x * 256 + threadIdx.x;
    if (n >= NN) return;
    const int* cx = cut_xs + n * FH;
    const unsigned char* iv = invalid + n * FH;
    int c = 0;
    int* on = g_off + n * FH;
#pragma unroll 9
    for (int h = 0; h < FH; h++) {
        int xv = cx[h];
        xv = min(max(xv, 0), FW - 1);
        if (!iv[h]) on[c++] = (h * FW + xv) * (JP / 4);
    }
    g_cnt[n] = c;
}

// ---------------------------------------------------------------------------
// k1: fold conv into head weights. grid (FH, 4): 16-ci slice per block.
// WW[ci,h,j] = sum_o conv_w[o,ci]*Wcat[o,h,j]; Bh[h,j] = sum_o conv_b[o]*Wcat[o,h,j]
// ---------------------------------------------------------------------------
__global__ void k_prep(const float* __restrict__ conv_w, const float* __restrict__ conv_b,
                       const float* __restrict__ cls_w,  const float* __restrict__ reg_w) {
    int h  = blockIdx.x;
    int by = blockIdx.y;            // ci slice
    int j  = threadIdx.x;           // 0..79
    int ty = threadIdx.y;           // 0..3
    __shared__ float sW[CC][JP];    // Wcat[o][j] for this h
    __shared__ float sc[CC][16];    // conv_w[o][by*16 + cl]

    int tid = ty * JP + j;          // 0..319
    for (int i = tid; i < CC * 16; i += 320) {
        int o = i >> 4, cl = i & 15;
        sc[o][cl] = conv_w[o * CC + by * 16 + cl];
    }
    for (int o = ty; o < CC; o += 4) {
        float v = 0.f;
        if (j < 2)          v = cls_w[(o * FH + h) * 2 + j];
        else if (j < JOUT)  v = reg_w[(o * FH + h) * 73 + (j - 2)];
        sW[o][j] = v;
    }
    __syncthreads();

    float a0 = 0.f, a1 = 0.f, a2 = 0.f, a3 = 0.f, accb = 0.f;
    bool do_b = (by == 0 && ty == 0);
#pragma unroll 8
    for (int o = 0; o < CC; o++) {
        float wv = sW[o][j];
        float4 c = *(const float4*)&sc[o][ty * 4];
        a0 += c.x * wv; a1 += c.y * wv; a2 += c.z * wv; a3 += c.w * wv;
        if (do_b) accb += conv_b[o] * wv;
    }
    int ci = by * 16 + ty * 4;
    g_WW[(h * CC + ci + 0) * JP + j] = a0;
    g_WW[(h * CC + ci + 1) * JP + j] = a1;
    g_WW[(h * CC + ci + 2) * JP + j] = a2;
    g_WW[(h * CC + ci + 3) * JP + j] = a3;
    if (do_b) g_Bh[h * JP + j] = accb;
}

// ---------------------------------------------------------------------------
// k2: P[b,h,w,j] = sum_ci x[b,ci,h,w]*WW[ci,h,j] + Bh[h,j]   (f32x2 packed)
// block (20,16): 4j x 5w tile per thread. grid (FH, BB).
// ---------------------------------------------------------------------------
__global__ void k_pcompute(const float* __restrict__ x) {
    int h = blockIdx.x, b = blockIdx.y;
    __shared__ float sx[CC][FW];
    __shared__ float sw[CC][JP];
    int tid = threadIdx.y * 20 + threadIdx.x;   // 0..319

    const float* xb  = x + ((b * CC) * FH + h) * FW;
    const float* wwh = g_WW + h * CC * JP;
    for (int i = tid; i < CC * FW; i += 320) {
        int ci = i / FW, w = i - ci * FW;
        sx[ci][w] = xb[ci * FH * FW + w];
        sw[ci][w] = wwh[i];
    }
    __syncthreads();

    int j0 = threadIdx.x * 4;   // 20*4 = 80 j
    int w0 = threadIdx.y * 5;   // 16*5 = 80 w
    unsigned long long acc0[5], acc1[5];
    unsigned long long z = pack2(0.f, 0.f);
#pragma unroll
    for (int v = 0; v < 5; v++) { acc0[v] = z; acc1[v] = z; }

#pragma unroll 4
    for (int ci = 0; ci < CC; ci++) {
        unsigned long long wa = *(const unsigned long long*)&sw[ci][j0];
        unsigned long long wb = *(const unsigned long long*)&sw[ci][j0 + 2];
#pragma unroll
        for (int v = 0; v < 5; v++) {
            float xs = sx[ci][w0 + v];
            unsigned long long xv = pack2(xs, xs);
            acc0[v] = fma2(xv, wa, acc0[v]);
            acc1[v] = fma2(xv, wb, acc1[v]);
        }
    }

    float4 bh = *(const float4*)&g_Bh[h * JP + j0];
    float* Pp = (float*)g_P + (size_t)((b * FH + h) * FW) * JP;
#pragma unroll
    for (int v = 0; v < 5; v++) {
        float4 r;
        float p0, p1;
        unpack2(acc0[v], p0, p1); r.x = p0 + bh.x; r.y = p1 + bh.y;
        unpack2(acc1[v], p0, p1); r.z = p0 + bh.z; r.w = p1 + bh.w;
        *(float4*)&Pp[(w0 + v) * JP + j0] = r;
    }
}

// ---------------------------------------------------------------------------
// k3: direct L2 gather over precompacted valid offsets.
// block (19,16): 16 anchors x 19 float4 j-lanes. grid (NN/16, BB).
// ---------------------------------------------------------------------------
__global__ void k_gather(const float* __restrict__ cls_b, const float* __restrict__ reg_b,
                         const float* __restrict__ anchors,
                         float* __restrict__ out) {
    int n0 = blockIdx.x * 16;
    int b  = blockIdx.y;
    __shared__ int offs[16][FH];
    __shared__ int cnt[16];

    int tx  = threadIdx.x;      // 0..18
    int a   = threadIdx.y;      // 0..15
    int tid = a * 19 + tx;
    for (int t = tid; t < 16 * FH; t += 304) {
        int aa = t / FH, hh = t - aa * FH;
        offs[aa][hh] = g_off[(n0 + aa) * FH + hh];
    }
    if (tid < 16) cnt[tid] = g_cnt[n0 + tid];
    __syncthreads();

    int n = n0 + a;
    const float4* Pb = g_P + (size_t)b * FH * FW * (JP / 4);

    int jb = tx * 4;
    float av[4];
#pragma unroll
    for (int u = 0; u < 4; u++) {
        int j = jb + u;
        av[u] = (j < 2) ? cls_b[j] : ((j < JOUT) ? reg_b[j - 2] : 0.f);
    }

    int c = cnt[a];
    int i = 0;
    for (; i + 5 <= c; i += 5) {
        float4 p0 = Pb[offs[a][i + 0] + tx];
        float4 p1 = Pb[offs[a][i + 1] + tx];
        float4 p2 = Pb[offs[a][i + 2] + tx];
        float4 p3 = Pb[offs[a][i + 3] + tx];
        float4 p4 = Pb[offs[a][i + 4] + tx];
        av[0] += p0.x + p1.x + p2.x + p3.x + p4.x;
        av[1] += p0.y + p1.y + p2.y + p3.y + p4.y;
        av[2] += p0.z + p1.z + p2.z + p3.z + p4.z;
        av[3] += p0.w + p1.w + p2.w + p3.w + p4.w;
    }
    for (; i < c; i++) {
        float4 p = Pb[offs[a][i] + tx];
        av[0] += p.x; av[1] += p.y; av[2] += p.z; av[3] += p.w;
    }

    int obase = (b * NN + n) * ODIM;
    const float* an = anchors + n * ODIM;
#pragma unroll
    for (int u = 0; u < 4; u++) {
        int j = jb + u;
        if (j < 2)          out[obase + j]     = av[u];
        else if (j < JOUT)  out[obase + j + 2] = an[j + 2] + av[u];
    }
    if (tx == 0) {
        out[obase + 2] = an[2];
        out[obase + 3] = an[3];
    }
}

// ---------------------------------------------------------------------------
extern "C" void kernel_launch(void* const* d_in, const int* in_sizes, int n_in,
                              void* d_out, int out_size) {
    const float* x       = (const float*)d_in[0];
    const float* conv_w  = (const float*)d_in[1];
    const float* conv_b  = (const float*)d_in[2];
    const float* cls_w   = (const float*)d_in[3];
    const float* cls_b   = (const float*)d_in[4];
    const float* reg_w   = (const float*)d_in[5];
    const float* reg_b   = (const float*)d_in[6];
    const float* anchors = (const float*)d_in[7];
    const int*   cut_xs  = (const int*)d_in[8];
    const unsigned char* invalid = (const unsigned char*)d_in[9];
    float* out = (float*)d_out;

    k_xpose   <<<(NN + 255) / 256, 256>>>(cut_xs, invalid);
    k_prep    <<<dim3(FH, 4),  dim3(80, 4)>>>(conv_w, conv_b, cls_w, reg_w);
    k_pcompute<<<dim3(FH, BB), dim3(20, 16)>>>(x);
    k_gather  <<<dim3(NN / 16, BB), dim3(19, 16)>>>(cls_b, reg_b, anchors, out);
}

// round 13
// speedup vs baseline: 1.4874x; 1.0316x over previous
#include <cuda_runtime.h>
#include <cstdint>

#define FH   45
#define FW   80
#define CC   64
#define BB   16
#define NN   2784
#define JOUT 75
#define JP   80          // P padded j-dim (20 float4)
#define ODIM 77

__device__ float  g_WW[FH * CC * JP];
__device__ float  g_Bh[FH * JP];
__device__ float4 g_P[BB * FH * FW * (JP/4)];
__device__ int    g_off[NN * FH];    // compacted valid offsets per anchor
__device__ int    g_cnt[NN];         // valid count per anchor

// ---------- f32x2 helpers (sm_103a packed fp32) ----------
__device__ __forceinline__ unsigned long long pack2(float a, float b) {
    unsigned long long r;
    asm("mov.b64 %0, {%1, %2};" : "=l"(r) : "f"(a), "f"(b));
    return r;
}
__device__ __forceinline__ void unpack2(unsigned long long v, float& a, float& b) {
    asm("mov.b64 {%0, %1}, %2;" : "=f"(a), "=f"(b) : "l"(v));
}
__device__ __forceinline__ unsigned long long fma2(unsigned long long a,
                                                   unsigned long long b,
                                                   unsigned long long c) {
    unsigned long long r;
    asm("fma.rn.f32x2 %0, %1, %2, %3;" : "=l"(r) : "l"(a), "l"(b), "l"(c));
    return r;
}

// ---------------------------------------------------------------------------
// k1: fold conv into head weights + (blockIdx.y==4) anchor compaction.
// grid (FH, 5), block (80, 4).
// ---------------------------------------------------------------------------
__global__ void k_prep_all(const float* __restrict__ conv_w, const float* __restrict__ conv_b,
                           const float* __restrict__ cls_w,  const float* __restrict__ reg_w,
                           const int* __restrict__ cut_xs,
                           const unsigned char* __restrict__ invalid) {
    if (blockIdx.y == 4) {
        // ---- anchor compaction: one thread per anchor ----
        int tid = threadIdx.y * 80 + threadIdx.x;
        int n = blockIdx.x * 320 + tid;
        if (n >= NN) return;
        const int* cx = cut_xs + n * FH;
        const unsigned char* iv = invalid + n * FH;
        int c = 0;
        int* on = g_off + n * FH;
#pragma unroll 9
        for (int h = 0; h < FH; h++) {
            int xv = cx[h];
            xv = min(max(xv, 0), FW - 1);
            if (!iv[h]) on[c++] = (h * FW + xv) * (JP / 4);
        }
        g_cnt[n] = c;
        return;
    }

    int h  = blockIdx.x;
    int by = blockIdx.y;            // ci slice 0..3
    int j  = threadIdx.x;           // 0..79
    int ty = threadIdx.y;           // 0..3
    __shared__ float sW[CC][JP];    // Wcat[o][j] for this h
    __shared__ float sc[CC][16];    // conv_w[o][by*16 + cl]

    int tid = ty * JP + j;          // 0..319
    for (int i = tid; i < CC * 16; i += 320) {
        int o = i >> 4, cl = i & 15;
        sc[o][cl] = conv_w[o * CC + by * 16 + cl];
    }
    for (int o = ty; o < CC; o += 4) {
        float v = 0.f;
        if (j < 2)          v = cls_w[(o * FH + h) * 2 + j];
        else if (j < JOUT)  v = reg_w[(o * FH + h) * 73 + (j - 2)];
        sW[o][j] = v;
    }
    __syncthreads();

    float a0 = 0.f, a1 = 0.f, a2 = 0.f, a3 = 0.f, accb = 0.f;
    bool do_b = (by == 0 && ty == 0);
#pragma unroll 8
    for (int o = 0; o < CC; o++) {
        float wv = sW[o][j];
        float4 c = *(const float4*)&sc[o][ty * 4];
        a0 += c.x * wv; a1 += c.y * wv; a2 += c.z * wv; a3 += c.w * wv;
        if (do_b) accb += conv_b[o] * wv;
    }
    int ci = by * 16 + ty * 4;
    g_WW[(h * CC + ci + 0) * JP + j] = a0;
    g_WW[(h * CC + ci + 1) * JP + j] = a1;
    g_WW[(h * CC + ci + 2) * JP + j] = a2;
    g_WW[(h * CC + ci + 3) * JP + j] = a3;
    if (do_b) g_Bh[h * JP + j] = accb;
}

// ---------------------------------------------------------------------------
// k2: P[b,h,w,j] = sum_ci x[b,ci,h,w]*WW[ci,h,j] + Bh[h,j]   (f32x2 packed)
// block (20,16): 4j x 5w tile per thread. grid (FH, BB).
// ---------------------------------------------------------------------------
__global__ void k_pcompute(const float* __restrict__ x) {
    int h = blockIdx.x, b = blockIdx.y;
    __shared__ float sx[CC][FW];
    __shared__ float sw[CC][JP];
    int tid = threadIdx.y * 20 + threadIdx.x;   // 0..319

    const float* xb  = x + ((b * CC) * FH + h) * FW;
    const float* wwh = g_WW + h * CC * JP;
    for (int i = tid; i < CC * FW; i += 320) {
        int ci = i / FW, w = i - ci * FW;
        sx[ci][w] = xb[ci * FH * FW + w];
        sw[ci][w] = wwh[i];
    }
    __syncthreads();

    int j0 = threadIdx.x * 4;   // 20*4 = 80 j
    int w0 = threadIdx.y * 5;   // 16*5 = 80 w
    unsigned long long acc0[5], acc1[5];
    unsigned long long z = pack2(0.f, 0.f);
#pragma unroll
    for (int v = 0; v < 5; v++) { acc0[v] = z; acc1[v] = z; }

#pragma unroll 4
    for (int ci = 0; ci < CC; ci++) {
        unsigned long long wa = *(const unsigned long long*)&sw[ci][j0];
        unsigned long long wb = *(const unsigned long long*)&sw[ci][j0 + 2];
#pragma unroll
        for (int v = 0; v < 5; v++) {
            float xs = sx[ci][w0 + v];
            unsigned long long xv = pack2(xs, xs);
            acc0[v] = fma2(xv, wa, acc0[v]);
            acc1[v] = fma2(xv, wb, acc1[v]);
        }
    }

    float4 bh = *(const float4*)&g_Bh[h * JP + j0];
    float* Pp = (float*)g_P + (size_t)((b * FH + h) * FW) * JP;
#pragma unroll
    for (int v = 0; v < 5; v++) {
        float4 r;
        float p0, p1;
        unpack2(acc0[v], p0, p1); r.x = p0 + bh.x; r.y = p1 + bh.y;
        unpack2(acc1[v], p0, p1); r.z = p0 + bh.z; r.w = p1 + bh.w;
        *(float4*)&Pp[(w0 + v) * JP + j0] = r;
    }
}

// ---------------------------------------------------------------------------
// k3: direct L2 gather, 2 batch-images per block (b, b+8).
// block (19,16): 16 anchors x 19 float4 j-lanes. grid (NN/16, BB/2).
// ---------------------------------------------------------------------------
__global__ void __launch_bounds__(304, 4)
k_gather(const float* __restrict__ cls_b, const float* __restrict__ reg_b,
         const float* __restrict__ anchors,
         float* __restrict__ out) {
    int n0 = blockIdx.x * 16;
    int b0 = blockIdx.y;           // 0..7
    int b1 = b0 + 8;
    __shared__ int offs[16][FH];
    __shared__ int cnt[16];

    int tx  = threadIdx.x;      // 0..18
    int a   = threadIdx.y;      // 0..15
    int tid = a * 19 + tx;
    for (int t = tid; t < 16 * FH; t += 304) {
        int aa = t / FH, hh = t - aa * FH;
        offs[aa][hh] = g_off[(n0 + aa) * FH + hh];
    }
    if (tid < 16) cnt[tid] = g_cnt[n0 + tid];
    __syncthreads();

    int n = n0 + a;
    const float4* Pb0 = g_P + (size_t)b0 * FH * FW * (JP / 4);
    const float4* Pb1 = g_P + (size_t)b1 * FH * FW * (JP / 4);

    int jb = tx * 4;
    float bias[4];
#pragma unroll
    for (int u = 0; u < 4; u++) {
        int j = jb + u;
        bias[u] = (j < 2) ? cls_b[j] : ((j < JOUT) ? reg_b[j - 2] : 0.f);
    }
    float av0[4], av1[4];
#pragma unroll
    for (int u = 0; u < 4; u++) { av0[u] = bias[u]; av1[u] = bias[u]; }

    int c = cnt[a];
    int i = 0;
    for (; i + 4 <= c; i += 4) {
        int o0 = offs[a][i + 0], o1 = offs[a][i + 1];
        int o2 = offs[a][i + 2], o3 = offs[a][i + 3];
        float4 p0 = Pb0[o0 + tx];
        float4 p1 = Pb0[o1 + tx];
        float4 p2 = Pb0[o2 + tx];
        float4 p3 = Pb0[o3 + tx];
        float4 q0 = Pb1[o0 + tx];
        float4 q1 = Pb1[o1 + tx];
        float4 q2 = Pb1[o2 + tx];
        float4 q3 = Pb1[o3 + tx];
        av0[0] += (p0.x + p1.x) + (p2.x + p3.x);
        av0[1] += (p0.y + p1.y) + (p2.y + p3.y);
        av0[2] += (p0.z + p1.z) + (p2.z + p3.z);
        av0[3] += (p0.w + p1.w) + (p2.w + p3.w);
        av1[0] += (q0.x + q1.x) + (q2.x + q3.x);
        av1[1] += (q0.y + q1.y) + (q2.y + q3.y);
        av1[2] += (q0.z + q1.z) + (q2.z + q3.z);
        av1[3] += (q0.w + q1.w) + (q2.w + q3.w);
    }
    for (; i < c; i++) {
        int o = offs[a][i];
        float4 p = Pb0[o + tx];
        float4 q = Pb1[o + tx];
        av0[0] += p.x; av0[1] += p.y; av0[2] += p.z; av0[3] += p.w;
        av1[0] += q.x; av1[1] += q.y; av1[2] += q.z; av1[3] += q.w;
    }

    const float* an = anchors + n * ODIM;
    float a2v = an[2], a3v = an[3];
    float anj[4];
#pragma unroll
    for (int u = 0; u < 4; u++) {
        int j = jb + u;
        anj[u] = (j >= 2 && j < JOUT) ? an[j + 2] : 0.f;
    }

#pragma unroll
    for (int s = 0; s < 2; s++) {
        int b = s ? b1 : b0;
        const float* av = s ? av1 : av0;
        int obase = (b * NN + n) * ODIM;
#pragma unroll
        for (int u = 0; u < 4; u++) {
            int j = jb + u;
            if (j < 2)          out[obase + j]     = av[u];
            else if (j < JOUT)  out[obase + j + 2] = anj[u] + av[u];
        }
        if (tx == 0) {
            out[obase + 2] = a2v;
            out[obase + 3] = a3v;
        }
    }
}

// ---------------------------------------------------------------------------
extern "C" void kernel_launch(void* const* d_in, const int* in_sizes, int n_in,
                              void* d_out, int out_size) {
    const float* x       = (const float*)d_in[0];
    const float* conv_w  = (const float*)d_in[1];
    const float* conv_b  = (const float*)d_in[2];
    const float* cls_w   = (const float*)d_in[3];
    const float* cls_b   = (const float*)d_in[4];
    const float* reg_w   = (const float*)d_in[5];
    const float* reg_b   = (const float*)d_in[6];
    const float* anchors = (const float*)d_in[7];
    const int*   cut_xs  = (const int*)d_in[8];
    const unsigned char* invalid = (const unsigned char*)d_in[9];
    float* out = (float*)d_out;

    k_prep_all<<<dim3(FH, 5),      dim3(80, 4)>>>(conv_w, conv_b, cls_w, reg_w, cut_xs, invalid);
    k_pcompute<<<dim3(FH, BB),     dim3(20, 16)>>>(x);
    k_gather  <<<dim3(NN / 16, 8), dim3(19, 16)>>>(cls_b, reg_b, anchors, out);
}

// round 14
// speedup vs baseline: 1.5172x; 1.0200x over previous
#include <cuda_runtime.h>
#include <cstdint>

#define FH   45
#define FW   80
#define CC   64
#define BB   16
#define NN   2784
#define JOUT 75
#define JP   80          // P padded j-dim (20 float4)
#define ODIM 77

__device__ float  g_WW[FH * CC * JP];
__device__ float  g_Bh[FH * JP];
__device__ float4 g_P[BB * FH * FW * (JP/4)];
__device__ int    g_off[NN * FH];    // compacted valid offsets per anchor
__device__ int    g_cnt[NN];         // valid count per anchor

// ---------- f32x2 helpers (sm_103a packed fp32) ----------
__device__ __forceinline__ unsigned long long pack2(float a, float b) {
    unsigned long long r;
    asm("mov.b64 %0, {%1, %2};" : "=l"(r) : "f"(a), "f"(b));
    return r;
}
__device__ __forceinline__ void unpack2(unsigned long long v, float& a, float& b) {
    asm("mov.b64 {%0, %1}, %2;" : "=f"(a), "=f"(b) : "l"(v));
}
__device__ __forceinline__ unsigned long long fma2(unsigned long long a,
                                                   unsigned long long b,
                                                   unsigned long long c) {
    unsigned long long r;
    asm("fma.rn.f32x2 %0, %1, %2, %3;" : "=l"(r) : "l"(a), "l"(b), "l"(c));
    return r;
}

// ---------------------------------------------------------------------------
// k1: weight fold, grid (FH, 5), block (20, 16) = 320 thr.
//  blockIdx.y 0..3: j-quarter jq. Block loads sW[64][20] (its j-cols only,
//  zero redundancy) + full conv_w (float4) and computes WW for all 64 ci.
//  blockIdx.y == 4: anchor compaction (one thread per anchor).
// ---------------------------------------------------------------------------
__global__ void k_prep_all(const float* __restrict__ conv_w, const float* __restrict__ conv_b,
                           const float* __restrict__ cls_w,  const float* __restrict__ reg_w,
                           const int* __restrict__ cut_xs,
                           const unsigned char* __restrict__ invalid) {
    int tx = threadIdx.x;            // 0..19
    int ty = threadIdx.y;            // 0..15
    int tid = ty * 20 + tx;          // 0..319

    if (blockIdx.y == 4) {
        int n = blockIdx.x * 320 + tid;
        if (n >= NN) return;
        const int* cx = cut_xs + n * FH;
        const unsigned char* iv = invalid + n * FH;
        int c = 0;
        int* on = g_off + n * FH;
#pragma unroll 9
        for (int h = 0; h < FH; h++) {
            int xv = cx[h];
            xv = min(max(xv, 0), FW - 1);
            if (!iv[h]) on[c++] = (h * FW + xv) * (JP / 4);
        }
        g_cnt[n] = c;
        return;
    }

    int h  = blockIdx.x;
    int jq = blockIdx.y;             // j-quarter 0..3
    __shared__ float sW[CC][20];     // Wcat[o][j-slice]
    __shared__ float sc[CC][CC];     // conv_w[o][ci] (float4-loaded)
    __shared__ float scb[CC];        // conv_b

    // conv_w: 4096 floats = 1024 float4
    {
        const float4* cw4 = (const float4*)conv_w;
        float4* sc4 = (float4*)&sc[0][0];
        for (int i = tid; i < 1024; i += 320) sc4[i] = cw4[i];
        if (tid < CC) scb[tid] = conv_b[tid];
    }
    // sW slice: 64 o-rows x 20 j-cols
    for (int t = tid; t < CC * 20; t += 320) {
        int o = t / 20, jj = t - o * 20;
        int j = jq * 20 + jj;
        float v = 0.f;
        if (j < 2)          v = cls_w[(o * FH + h) * 2 + j];
        else if (j < JOUT)  v = reg_w[(o * FH + h) * 73 + (j - 2)];
        sW[o][jj] = v;
    }
    __syncthreads();

    int j  = jq * 20 + tx;
    int ci = ty * 4;
    unsigned long long acc01 = pack2(0.f, 0.f), acc23 = pack2(0.f, 0.f);
    float accb = 0.f;
    bool do_b = (ty == 0);
#pragma unroll 8
    for (int o = 0; o < CC; o++) {
        float wv = sW[o][tx];
        unsigned long long pw = pack2(wv, wv);
        const unsigned long long* cp = (const unsigned long long*)&sc[o][ci];
        acc01 = fma2(cp[0], pw, acc01);
        acc23 = fma2(cp[1], pw, acc23);
        if (do_b) accb += scb[o] * wv;
    }
    float a0, a1, a2, a3;
    unpack2(acc01, a0, a1);
    unpack2(acc23, a2, a3);
    g_WW[(h * CC + ci + 0) * JP + j] = a0;
    g_WW[(h * CC + ci + 1) * JP + j] = a1;
    g_WW[(h * CC + ci + 2) * JP + j] = a2;
    g_WW[(h * CC + ci + 3) * JP + j] = a3;
    if (do_b) g_Bh[h * JP + j] = accb;
}

// ---------------------------------------------------------------------------
// k2: P[b,h,w,j] = sum_ci x[b,ci,h,w]*WW[ci,h,j] + Bh[h,j]   (f32x2 packed)
// block (20,16): 4j x 5w tile per thread. grid (FH, BB). float4 smem fills.
// ---------------------------------------------------------------------------
__global__ void k_pcompute(const float* __restrict__ x) {
    int h = blockIdx.x, b = blockIdx.y;
    __shared__ float sx[CC][FW];
    __shared__ float sw[CC][JP];
    int tid = threadIdx.y * 20 + threadIdx.x;   // 0..319

    // vectorized fills: 1280 float4 each
    {
        const float4* xb4  = (const float4*)(x + ((size_t)(b * CC) * FH + h) * FW);
        const float4* ww4  = (const float4*)(g_WW + h * CC * JP);
        float4* sx4 = (float4*)&sx[0][0];
        float4* sw4 = (float4*)&sw[0][0];
#pragma unroll
        for (int i = tid; i < CC * FW / 4; i += 320) {
            int ci = i / 20, w4 = i - ci * 20;
            sx4[i] = xb4[(size_t)ci * (FH * FW / 4) + w4];
            sw4[i] = ww4[i];
        }
    }
    __syncthreads();

    int j0 = threadIdx.x * 4;   // 20*4 = 80 j
    int w0 = threadIdx.y * 5;   // 16*5 = 80 w
    unsigned long long acc0[5], acc1[5];
    unsigned long long z = pack2(0.f, 0.f);
#pragma unroll
    for (int v = 0; v < 5; v++) { acc0[v] = z; acc1[v] = z; }

#pragma unroll 4
    for (int ci = 0; ci < CC; ci++) {
        unsigned long long wa = *(const unsigned long long*)&sw[ci][j0];
        unsigned long long wb = *(const unsigned long long*)&sw[ci][j0 + 2];
#pragma unroll
        for (int v = 0; v < 5; v++) {
            float xs = sx[ci][w0 + v];
            unsigned long long xv = pack2(xs, xs);
            acc0[v] = fma2(xv, wa, acc0[v]);
            acc1[v] = fma2(xv, wb, acc1[v]);
        }
    }

    float4 bh = *(const float4*)&g_Bh[h * JP + j0];
    float* Pp = (float*)g_P + (size_t)((b * FH + h) * FW) * JP;
#pragma unroll
    for (int v = 0; v < 5; v++) {
        float4 r;
        float p0, p1;
        unpack2(acc0[v], p0, p1); r.x = p0 + bh.x; r.y = p1 + bh.y;
        unpack2(acc1[v], p0, p1); r.z = p0 + bh.z; r.w = p1 + bh.w;
        *(float4*)&Pp[(w0 + v) * JP + j0] = r;
    }
}

// ---------------------------------------------------------------------------
// k3: direct L2 gather, 2 batch-images per block (b, b+8).
// block (19,16): 16 anchors x 19 float4 j-lanes. grid (NN/16, BB/2).
// ---------------------------------------------------------------------------
__global__ void __launch_bounds__(304, 4)
k_gather(const float* __restrict__ cls_b, const float* __restrict__ reg_b,
         const float* __restrict__ anchors,
         float* __restrict__ out) {
    int n0 = blockIdx.x * 16;
    int b0 = blockIdx.y;           // 0..7
    int b1 = b0 + 8;
    __shared__ int offs[16][FH];
    __shared__ int cnt[16];

    int tx  = threadIdx.x;      // 0..18
    int a   = threadIdx.y;      // 0..15
    int tid = a * 19 + tx;
    for (int t = tid; t < 16 * FH; t += 304) {
        int aa = t / FH, hh = t - aa * FH;
        offs[aa][hh] = g_off[(n0 + aa) * FH + hh];
    }
    if (tid < 16) cnt[tid] = g_cnt[n0 + tid];
    __syncthreads();

    int n = n0 + a;
    const float4* Pb0 = g_P + (size_t)b0 * FH * FW * (JP / 4);
    const float4* Pb1 = g_P + (size_t)b1 * FH * FW * (JP / 4);

    int jb = tx * 4;
    float bias[4];
#pragma unroll
    for (int u = 0; u < 4; u++) {
        int j = jb + u;
        bias[u] = (j < 2) ? cls_b[j] : ((j < JOUT) ? reg_b[j - 2] : 0.f);
    }
    float av0[4], av1[4];
#pragma unroll
    for (int u = 0; u < 4; u++) { av0[u] = bias[u]; av1[u] = bias[u]; }

    int c = cnt[a];
    int i = 0;
    for (; i + 4 <= c; i += 4) {
        int o0 = offs[a][i + 0], o1 = offs[a][i + 1];
        int o2 = offs[a][i + 2], o3 = offs[a][i + 3];
        float4 p0 = Pb0[o0 + tx];
        float4 p1 = Pb0[o1 + tx];
        float4 p2 = Pb0[o2 + tx];
        float4 p3 = Pb0[o3 + tx];
        float4 q0 = Pb1[o0 + tx];
        float4 q1 = Pb1[o1 + tx];
        float4 q2 = Pb1[o2 + tx];
        float4 q3 = Pb1[o3 + tx];
        av0[0] += (p0.x + p1.x) + (p2.x + p3.x);
        av0[1] += (p0.y + p1.y) + (p2.y + p3.y);
        av0[2] += (p0.z + p1.z) + (p2.z + p3.z);
        av0[3] += (p0.w + p1.w) + (p2.w + p3.w);
        av1[0] += (q0.x + q1.x) + (q2.x + q3.x);
        av1[1] += (q0.y + q1.y) + (q2.y + q3.y);
        av1[2] += (q0.z + q1.z) + (q2.z + q3.z);
        av1[3] += (q0.w + q1.w) + (q2.w + q3.w);
    }
    for (; i < c; i++) {
        int o = offs[a][i];
        float4 p = Pb0[o + tx];
        float4 q = Pb1[o + tx];
        av0[0] += p.x; av0[1] += p.y; av0[2] += p.z; av0[3] += p.w;
        av1[0] += q.x; av1[1] += q.y; av1[2] += q.z; av1[3] += q.w;
    }

    const float* an = anchors + n * ODIM;
    float a2v = an[2], a3v = an[3];
    float anj[4];
#pragma unroll
    for (int u = 0; u < 4; u++) {
        int j = jb + u;
        anj[u] = (j >= 2 && j < JOUT) ? an[j + 2] : 0.f;
    }

#pragma unroll
    for (int s = 0; s < 2; s++) {
        int b = s ? b1 : b0;
        const float* av = s ? av1 : av0;
        int obase = (b * NN + n) * ODIM;
#pragma unroll
        for (int u = 0; u < 4; u++) {
            int j = jb + u;
            if (j < 2)          out[obase + j]     = av[u];
            else if (j < JOUT)  out[obase + j + 2] = anj[u] + av[u];
        }
        if (tx == 0) {
            out[obase + 2] = a2v;
            out[obase + 3] = a3v;
        }
    }
}

// ---------------------------------------------------------------------------
extern "C" void kernel_launch(void* const* d_in, const int* in_sizes, int n_in,
                              void* d_out, int out_size) {
    const float* x       = (const float*)d_in[0];
    const float* conv_w  = (const float*)d_in[1];
    const float* conv_b  = (const float*)d_in[2];
    const float* cls_w   = (const float*)d_in[3];
    const float* cls_b   = (const float*)d_in[4];
    const float* reg_w   = (const float*)d_in[5];
    const float* reg_b   = (const float*)d_in[6];
    const float* anchors = (const float*)d_in[7];
    const int*   cut_xs  = (const int*)d_in[8];
    const unsigned char* invalid = (const unsigned char*)d_in[9];
    float* out = (float*)d_out;

    k_prep_all<<<dim3(FH, 5),      dim3(20, 16)>>>(conv_w, conv_b, cls_w, reg_w, cut_xs, invalid);
    k_pcompute<<<dim3(FH, BB),     dim3(20, 16)>>>(x);
    k_gather  <<<dim3(NN / 16, 8), dim3(19, 16)>>>(cls_b, reg_b, anchors, out);
}